// round 3
// baseline (speedup 1.0000x reference)
#include <cuda_runtime.h>

#define BB 8
#define NN 256
#define DD 256
#define HH 128
#define RR 8

// Scratch (allocation-free rule: __device__ globals)
__device__ float g_pi[BB * NN * HH];   // proj_i
__device__ float g_pj[BB * NN * HH];   // proj_j + b1

typedef unsigned long long u64;
union F2U { float2 f; u64 u; };

__device__ __forceinline__ u64 f2add_u(u64 a, u64 b) {
    u64 d;
    asm("add.rn.f32x2 %0, %1, %2;" : "=l"(d) : "l"(a), "l"(b));
    return d;
}
__device__ __forceinline__ u64 f2fma_u(u64 a, u64 b, u64 c) {
    u64 d;
    asm("fma.rn.f32x2 %0, %1, %2, %3;" : "=l"(d) : "l"(a), "l"(b), "l"(c));
    return d;
}
__device__ __forceinline__ u64 fdup(float x) {
    u64 d;
    asm("mov.b64 %0, {%1, %1};" : "=l"(d) : "f"(x));
    return d;
}

// -------------------------------------------------------------------------
// Phase A: proj_i = slots @ W1[:D], proj_j = slots @ W1[D:] + b1
// Grid: 128 blocks x 256 threads. Block = 16 rows of the [2048,256] input.
// Thread t: column h = t&127 of (t<128 ? proj_i : proj_j), all 16 rows,
// accumulated as 8 f32x2 (row pairs).
// -------------------------------------------------------------------------
__global__ __launch_bounds__(256) void proj_kernel(
    const float* __restrict__ slots,
    const float* __restrict__ W1,
    const float* __restrict__ b1)
{
    __shared__ float a_s[256 * 18];   // [k][row], 16 rows padded to 18

    const int t = threadIdx.x;
    const int row0 = blockIdx.x * 16;

    #pragma unroll
    for (int ii = 0; ii < 16; ii++) {
        int idx = t + ii * 256;
        int rr = idx >> 8;          // 0..15
        int k  = idx & 255;         // 0..255
        a_s[k * 18 + rr] = slots[(row0 + rr) * DD + k];
    }
    __syncthreads();

    const int h    = t & 127;
    const int ispj = t >> 7;
    const float* wp = W1 + ispj * (DD * HH) + h;   // W1[k][h], row stride HH

    u64 acc[8];
    #pragma unroll
    for (int r = 0; r < 8; r++) acc[r] = 0ull;

    #pragma unroll 4
    for (int k = 0; k < 256; k++) {
        float w = __ldg(wp + k * HH);
        u64 wd = fdup(w);
        #pragma unroll
        for (int r = 0; r < 8; r++) {
            u64 a2 = *(const u64*)(a_s + k * 18 + 2 * r);
            acc[r] = f2fma_u(a2, wd, acc[r]);
        }
    }

    float bias = ispj ? b1[h] : 0.0f;
    float* dst = ispj ? g_pj : g_pi;
    #pragma unroll
    for (int r = 0; r < 8; r++) {
        F2U cv; cv.u = acc[r];
        int row = row0 + 2 * r;
        dst[row * HH + h]       = cv.f.x + bias;
        dst[(row + 1) * HH + h] = cv.f.y + bias;
    }
}

// -------------------------------------------------------------------------
// Phase B: out[b,i,j,r] = sigmoid( sum_k relu(pi[b,i,k]+pj[b,j,k]) * W2[k,r] + b2[r] )
// Grid (jt, it, b) = (8, 8, 8); block 256 threads covers a 32x32 pair tile;
// each thread: 2i x 2j = 4 pairs (i = ty, ty+16; j = tx, tx+16).
// f32x2 packing over k: acc lanes hold even/odd-k partial sums.
// relu trick: 2*relu(x) = x + |x| (exact), with 0.5*W2 pre-stored (exact).
// -------------------------------------------------------------------------
__global__ __launch_bounds__(256, 2) void pair_kernel(
    const float* __restrict__ W2,
    const float* __restrict__ b2v,
    float* __restrict__ out)
{
    __shared__ float pi_s[32 * 130];  // [i][k], pad 130 for conflict-free LDS.64
    __shared__ float pj_s[32 * 130];  // [j][k]
    __shared__ u64   w2p[64 * 8];     // [k/2][r] = {0.5*W2[k][r], 0.5*W2[k+1][r]}

    const int t  = threadIdx.x;
    const int jt = blockIdx.x, it = blockIdx.y, b = blockIdx.z;
    const int ibase = b * NN + it * 32;
    const int jbase = b * NN + jt * 32;

    #pragma unroll
    for (int ii = 0; ii < 16; ii++) {
        int idx = t + ii * 256;
        int r = idx >> 7;          // 0..31
        int k = idx & 127;
        pi_s[r * 130 + k] = g_pi[(ibase + r) * HH + k];
        pj_s[r * 130 + k] = g_pj[(jbase + r) * HH + k];
    }
    #pragma unroll
    for (int ii = 0; ii < 2; ii++) {
        int idx = t + ii * 256;     // 0..511
        int k2 = idx >> 3, r = idx & 7;
        F2U cv;
        cv.f = make_float2(0.5f * W2[(2 * k2) * RR + r],
                           0.5f * W2[(2 * k2 + 1) * RR + r]);
        w2p[idx] = cv.u;
    }
    __syncthreads();

    const int tx = t & 15, ty = t >> 4;
    const float* pA = pi_s + ty * 130;
    const float* pB = pi_s + (ty + 16) * 130;
    const float* pC = pj_s + tx * 130;
    const float* pD = pj_s + (tx + 16) * 130;

    u64 acc[4][8];
    #pragma unroll
    for (int p = 0; p < 4; p++)
        #pragma unroll
        for (int r = 0; r < 8; r++) acc[p][r] = 0ull;

    const u64 ABSM = 0x7FFFFFFF7FFFFFFFULL;

    #pragma unroll 4
    for (int k = 0; k < 128; k += 2) {
        u64 piA = *(const u64*)(pA + k);
        u64 piB = *(const u64*)(pB + k);
        u64 pjA = *(const u64*)(pC + k);
        u64 pjB = *(const u64*)(pD + k);

        u64 s00 = f2add_u(piA, pjA);
        u64 s01 = f2add_u(piA, pjB);
        u64 s10 = f2add_u(piB, pjA);
        u64 s11 = f2add_u(piB, pjB);

        // 2*relu(x) = x + |x|  (bit-exact; compensated by 0.5*W2)
        u64 h00 = f2add_u(s00, s00 & ABSM);
        u64 h01 = f2add_u(s01, s01 & ABSM);
        u64 h10 = f2add_u(s10, s10 & ABSM);
        u64 h11 = f2add_u(s11, s11 & ABSM);

        const u64* wrow = w2p + (k >> 1) * 8;
        #pragma unroll
        for (int r = 0; r < 8; r++) {
            u64 w = wrow[r];
            acc[0][r] = f2fma_u(h00, w, acc[0][r]);
            acc[1][r] = f2fma_u(h01, w, acc[1][r]);
            acc[2][r] = f2fma_u(h10, w, acc[2][r]);
            acc[3][r] = f2fma_u(h11, w, acc[3][r]);
        }
    }

    float bb[8];
    #pragma unroll
    for (int r = 0; r < 8; r++) bb[r] = b2v[r];

    #pragma unroll
    for (int p = 0; p < 4; p++) {
        int gi = it * 32 + ty + ((p >> 1) << 4);
        int gj = jt * 32 + tx + ((p & 1) << 4);
        float* op = out + (((size_t)(b * NN + gi) * NN + gj) << 3);

        float o[8];
        #pragma unroll
        for (int r = 0; r < 8; r++) {
            F2U cv; cv.u = acc[p][r];
            float s = cv.f.x + cv.f.y + bb[r];
            o[r] = __fdividef(1.0f, 1.0f + __expf(-s));
        }
        *(float4*)op       = make_float4(o[0], o[1], o[2], o[3]);
        *(float4*)(op + 4) = make_float4(o[4], o[5], o[6], o[7]);
    }
}

extern "C" void kernel_launch(void* const* d_in, const int* in_sizes, int n_in,
                              void* d_out, int out_size)
{
    const float* slots = (const float*)d_in[0];
    const float* W1    = (const float*)d_in[1];
    const float* b1    = (const float*)d_in[2];
    const float* W2    = (const float*)d_in[3];
    const float* b2    = (const float*)d_in[4];
    float* out = (float*)d_out;

    proj_kernel<<<128, 256>>>(slots, W1, b1);

    dim3 grid(8, 8, 8);   // (jt, it, b)
    pair_kernel<<<grid, 256>>>(W2, b2, out);
}

// round 5
// speedup vs baseline: 2.3657x; 2.3657x over previous
#include <cuda_runtime.h>
#include <cuda_fp16.h>
#include <cstdint>

#define NN 256
#define HH 128
#define RR 8

typedef unsigned long long u64;
union F2U { float2 f; u64 u; };

// packed f16x2 proj outputs: [2048 rows][64 kpairs]; lo half = even k
__device__ uint32_t g_pi_h[2048 * 64];
__device__ uint32_t g_pj_h[2048 * 64];

// ---------------- helpers ----------------
__device__ __forceinline__ u64 f2fma_u(u64 a, u64 b, u64 c) {
    u64 d; asm("fma.rn.f32x2 %0, %1, %2, %3;" : "=l"(d) : "l"(a), "l"(b), "l"(c)); return d;
}
__device__ __forceinline__ u64 fdup(float x) {
    u64 d; asm("mov.b64 %0, {%1, %1};" : "=l"(d) : "f"(x)); return d;
}
__device__ __forceinline__ uint32_t hadd2(uint32_t a, uint32_t b) {
    uint32_t d; asm("add.rn.f16x2 %0, %1, %2;" : "=r"(d) : "r"(a), "r"(b)); return d;
}
__device__ __forceinline__ uint32_t hmax2(uint32_t a, uint32_t b) {
    uint32_t d; asm("max.f16x2 %0, %1, %2;" : "=r"(d) : "r"(a), "r"(b)); return d;
}
__device__ __forceinline__ uint32_t pack_f16x2(float lo, float hi) {
    uint32_t d; asm("cvt.rn.f16x2.f32 %0, %1, %2;" : "=r"(d) : "f"(hi), "f"(lo)); return d;
}
__device__ __forceinline__ void mma16816(float* d, uint32_t a0, uint32_t a1,
                                         uint32_t a2, uint32_t a3,
                                         uint32_t b0, uint32_t b1) {
    asm("mma.sync.aligned.m16n8k16.row.col.f32.f16.f16.f32 "
        "{%0,%1,%2,%3}, {%4,%5,%6,%7}, {%8,%9}, {%0,%1,%2,%3};"
        : "+f"(d[0]), "+f"(d[1]), "+f"(d[2]), "+f"(d[3])
        : "r"(a0), "r"(a1), "r"(a2), "r"(a3), "r"(b0), "r"(b1));
}

// -------------------------------------------------------------------------
// Phase A: proj = slots[2048,256] @ W1cat[256,256] (+b1 on pj half), fp32 GEMM,
// epilogue packs f16x2. grid (4 col-tiles, 32 row-tiles) x 256 thr, 64x64 tile.
// -------------------------------------------------------------------------
__global__ __launch_bounds__(256) void proj_kernel(
    const float* __restrict__ slots,
    const float* __restrict__ W1,
    const float* __restrict__ b1)
{
    __shared__ __align__(8) float As[32 * 65];   // [k][row]
    __shared__ __align__(8) float Bs[32 * 66];   // [k][col]

    const int tid = threadIdx.x;
    const int ct = blockIdx.x, rt = blockIdx.y;
    const int row0 = rt * 64;
    const int which = ct >> 1;             // 0 -> pi, 1 -> pj
    const int hbase = (ct & 1) * 64;
    const int tx = tid & 15, ty = tid >> 4;

    u64 acc[4][2];
    #pragma unroll
    for (int p = 0; p < 4; p++) { acc[p][0] = 0ull; acc[p][1] = 0ull; }

    for (int kk = 0; kk < 256; kk += 32) {
        {
            int k = tid & 31, r0 = tid >> 5;
            #pragma unroll
            for (int r = r0; r < 64; r += 8)
                As[k * 65 + r] = slots[(size_t)(row0 + r) * 256 + kk + k];
        }
        {
            int c = tid & 63, k0 = tid >> 6;
            #pragma unroll
            for (int k = k0; k < 32; k += 4)
                Bs[k * 66 + c] = W1[(size_t)(which * 256 + kk + k) * HH + hbase + c];
        }
        __syncthreads();

        #pragma unroll
        for (int k = 0; k < 32; k++) {
            u64 bA = *(const u64*)(Bs + k * 66 + 2 * tx);
            u64 bB = *(const u64*)(Bs + k * 66 + 2 * tx + 32);
            #pragma unroll
            for (int p = 0; p < 4; p++) {
                u64 ad = fdup(As[k * 65 + ty + 16 * p]);
                acc[p][0] = f2fma_u(ad, bA, acc[p][0]);
                acc[p][1] = f2fma_u(ad, bB, acc[p][1]);
            }
        }
        __syncthreads();
    }

    uint32_t* dst = which ? g_pj_h : g_pi_h;
    float2 bias0 = make_float2(0.f, 0.f), bias1 = make_float2(0.f, 0.f);
    if (which) {
        bias0 = *(const float2*)(b1 + hbase + 2 * tx);
        bias1 = *(const float2*)(b1 + hbase + 2 * tx + 32);
    }
    const int cbase = (hbase >> 1) + tx;    // u32 (f16x2) column; lo = even h
    #pragma unroll
    for (int p = 0; p < 4; p++) {
        int row = row0 + ty + 16 * p;
        F2U c0; c0.u = acc[p][0];
        F2U c1; c1.u = acc[p][1];
        dst[row * 64 + cbase]      = pack_f16x2(c0.f.x + bias0.x, c0.f.y + bias0.y);
        dst[row * 64 + cbase + 16] = pack_f16x2(c1.f.x + bias1.x, c1.f.y + bias1.y);
    }
}

// -------------------------------------------------------------------------
// Phase B (HMMA): CTA = (itile of 16, b), 8 warps; warp w owns j in [32w,32w+32)
// as 2 jtiles of 16. mma.m16n8k16: M=16 j, N=8 r, K=16 h (8 k-steps).
// pj fragments hoisted in regs across all 16 i; A = relu(pi+pj) built as f16x2
// directly in fragment layout (HADD2+HMAX2). Epilogue: +b2, sigmoid, STG.64.
// -------------------------------------------------------------------------
#define PJ_STRIDE 68   // u32 stride; 68 % 32 == 4 -> conflict-free frag LDS

__global__ __launch_bounds__(256, 1) void pair_mma_kernel(
    const float* __restrict__ W2,
    const float* __restrict__ b2,
    float* __restrict__ out)
{
    extern __shared__ uint32_t smem[];
    uint32_t* pj_s = smem;                 // [256][PJ_STRIDE]
    uint32_t* pi_s = smem + 256 * PJ_STRIDE;  // [16][PJ_STRIDE]

    const int tid = threadIdx.x;
    const int w = tid >> 5;                // warp 0..7
    const int lane = tid & 31;
    const int g = lane >> 2;               // group id 0..7
    const int t = lane & 3;                // thread-in-group
    const int itile = blockIdx.x, b = blockIdx.y;

    // stage pj (all 256 j rows of this batch) and pi (16 i rows), u64 coalesced
    {
        const u64* src = (const u64*)(g_pj_h + ((size_t)b * NN << 6));
        #pragma unroll
        for (int it = 0; it < 32; it++) {
            int idx = tid + it * 256;      // 0..8191
            int row = idx >> 5, c2 = idx & 31;
            *(u64*)(pj_s + row * PJ_STRIDE + 2 * c2) = src[idx];
        }
        const u64* srci = (const u64*)(g_pi_h + (((size_t)b * NN + itile * 16) << 6));
        #pragma unroll
        for (int it = 0; it < 2; it++) {
            int idx = tid + it * 256;      // 0..511
            int row = idx >> 5, c2 = idx & 31;
            *(u64*)(pi_s + row * PJ_STRIDE + 2 * c2) = srci[idx];
        }
    }

    // W2 fragments (col-major B frag): b0 = {W2[k0][g], W2[k0+1][g]}, k0 = 16s+2t
    uint32_t w2f[8][2];
    #pragma unroll
    for (int s = 0; s < 8; s++) {
        int k0 = 16 * s + 2 * t;
        w2f[s][0] = pack_f16x2(W2[k0 * RR + g],       W2[(k0 + 1) * RR + g]);
        w2f[s][1] = pack_f16x2(W2[(k0 + 8) * RR + g], W2[(k0 + 9) * RR + g]);
    }
    const float2 b2p = *(const float2*)(b2 + 2 * t);

    __syncthreads();

    // hoist pj fragments: [jt][s][{row g lo, row g+8 lo, row g hi, row g+8 hi}]
    uint32_t pjf[2][8][4];
    #pragma unroll
    for (int jt = 0; jt < 2; jt++) {
        const uint32_t* r0 = pj_s + (w * 32 + jt * 16 + g) * PJ_STRIDE;
        const uint32_t* r8 = r0 + 8 * PJ_STRIDE;
        #pragma unroll
        for (int s = 0; s < 8; s++) {
            pjf[jt][s][0] = r0[t + 8 * s];
            pjf[jt][s][1] = r8[t + 8 * s];
            pjf[jt][s][2] = r0[t + 8 * s + 4];
            pjf[jt][s][3] = r8[t + 8 * s + 4];
        }
    }

    const size_t obase = (((size_t)b * NN + itile * 16) * NN + w * 32) * RR;

    #pragma unroll 2
    for (int i = 0; i < 16; i++) {
        uint32_t piv[16];
        {
            const uint32_t* pir = pi_s + i * PJ_STRIDE;
            #pragma unroll
            for (int s = 0; s < 8; s++) {
                piv[2 * s]     = pir[t + 8 * s];
                piv[2 * s + 1] = pir[t + 8 * s + 4];
            }
        }
        #pragma unroll
        for (int jt = 0; jt < 2; jt++) {
            float d[4] = {0.f, 0.f, 0.f, 0.f};
            #pragma unroll
            for (int s = 0; s < 8; s++) {
                uint32_t lo = piv[2 * s], hi = piv[2 * s + 1];
                uint32_t a0 = hmax2(hadd2(pjf[jt][s][0], lo), 0u);
                uint32_t a1 = hmax2(hadd2(pjf[jt][s][1], lo), 0u);
                uint32_t a2 = hmax2(hadd2(pjf[jt][s][2], hi), 0u);
                uint32_t a3 = hmax2(hadd2(pjf[jt][s][3], hi), 0u);
                mma16816(d, a0, a1, a2, a3, w2f[s][0], w2f[s][1]);
            }
            // epilogue: rows g (d0,d1) and g+8 (d2,d3), cols r=2t,2t+1
            float s0 = d[0] + b2p.x, s1 = d[1] + b2p.y;
            float s2 = d[2] + b2p.x, s3 = d[3] + b2p.y;
            float2 o0 = make_float2(__fdividef(1.f, 1.f + __expf(-s0)),
                                    __fdividef(1.f, 1.f + __expf(-s1)));
            float2 o1 = make_float2(__fdividef(1.f, 1.f + __expf(-s2)),
                                    __fdividef(1.f, 1.f + __expf(-s3)));
            float* op = out + obase + (size_t)i * NN * RR + (jt * 16) * RR + 2 * t;
            *(float2*)(op + g * RR)       = o0;
            *(float2*)(op + (g + 8) * RR) = o1;
        }
    }
}

#define PAIR_SMEM ((256 + 16) * PJ_STRIDE * 4)

extern "C" void kernel_launch(void* const* d_in, const int* in_sizes, int n_in,
                              void* d_out, int out_size)
{
    const float* slots = (const float*)d_in[0];
    const float* W1    = (const float*)d_in[1];
    const float* b1    = (const float*)d_in[2];
    const float* W2    = (const float*)d_in[3];
    const float* b2    = (const float*)d_in[4];
    float* out = (float*)d_out;

    static int smem_set = 0;
    if (!smem_set) {
        cudaFuncSetAttribute(pair_mma_kernel,
                             cudaFuncAttributeMaxDynamicSharedMemorySize, PAIR_SMEM);
        smem_set = 1;
    }

    proj_kernel<<<dim3(4, 32), 256>>>(slots, W1, b1);
    pair_mma_kernel<<<dim3(16, 8), 256, PAIR_SMEM>>>(W2, b2, out);
}

// round 6
// speedup vs baseline: 3.2878x; 1.3898x over previous
#include <cuda_runtime.h>
#include <cuda_fp16.h>
#include <cstdint>

#define NN 256
#define HH 128
#define RR 8

typedef unsigned long long u64;

// packed f16x2 proj outputs: [2048 rows][64 kpairs]; lo half = even k
__device__ uint32_t g_pi_h[2048 * 64];
__device__ uint32_t g_pj_h[2048 * 64];

// ---------------- helpers ----------------
__device__ __forceinline__ uint32_t hadd2(uint32_t a, uint32_t b) {
    uint32_t d; asm("add.rn.f16x2 %0, %1, %2;" : "=r"(d) : "r"(a), "r"(b)); return d;
}
__device__ __forceinline__ uint32_t hmax2(uint32_t a, uint32_t b) {
    uint32_t d; asm("max.f16x2 %0, %1, %2;" : "=r"(d) : "r"(a), "r"(b)); return d;
}
__device__ __forceinline__ uint32_t pack_f16x2(float lo, float hi) {
    uint32_t d; asm("cvt.rn.f16x2.f32 %0, %1, %2;" : "=r"(d) : "f"(hi), "f"(lo)); return d;
}
__device__ __forceinline__ void mma16816(float* d, uint32_t a0, uint32_t a1,
                                         uint32_t a2, uint32_t a3,
                                         uint32_t b0, uint32_t b1) {
    asm("mma.sync.aligned.m16n8k16.row.col.f32.f16.f16.f32 "
        "{%0,%1,%2,%3}, {%4,%5,%6,%7}, {%8,%9}, {%0,%1,%2,%3};"
        : "+f"(d[0]), "+f"(d[1]), "+f"(d[2]), "+f"(d[3])
        : "r"(a0), "r"(a1), "r"(a2), "r"(a3), "r"(b0), "r"(b1));
}
// sigmoid(x) = 0.5 + 0.5*tanh(0.5*x); hb carries 0.5*b2 folded in
__device__ __forceinline__ float sigm(float x, float hb) {
    float t, a = fmaf(0.5f, x, hb);
    asm("tanh.approx.f32 %0, %1;" : "=f"(t) : "f"(a));
    return fmaf(0.5f, t, 0.5f);
}

// -------------------------------------------------------------------------
// Phase A (HMMA): proj = slots[2048,256] @ W1cat[256,256] (+b1 on pj half).
// CTA tile 32M x 64N, full K=256 staged as f16x2 in smem. grid (4 ct, 64 rt).
// Fragment layout identical to the (validated) pair kernel mapping.
// -------------------------------------------------------------------------
#define PSTRIDE 132                       // u32 stride; 132%32==4 -> conflict-free
#define PROJ_SMEM ((32 + 64) * PSTRIDE * 4)

__global__ __launch_bounds__(256) void proj_kernel(
    const float* __restrict__ slots,
    const float* __restrict__ W1,
    const float* __restrict__ b1)
{
    extern __shared__ uint32_t ps[];
    uint32_t* As = ps;                    // [32 rows][128 kpairs]
    uint32_t* Ws = ps + 32 * PSTRIDE;     // [64 ncols][128 kpairs]
    __half* Ws_h = (__half*)Ws;

    const int tid = threadIdx.x;
    const int ct = blockIdx.x, rt = blockIdx.y;
    const int row0 = rt * 32;
    const int which = ct >> 1;            // 0 -> pi, 1 -> pj
    const int hbase = (ct & 1) * 64;

    // stage slots rows [row0, row0+32), all K=256, converting to f16x2
    {
        const float2* sp = (const float2*)(slots + (size_t)row0 * 256);
        #pragma unroll
        for (int it = 0; it < 16; it++) {
            int e = tid + it * 256;       // 0..4095
            int r = e >> 7, c2 = e & 127;
            float2 v = sp[r * 128 + c2];
            As[r * PSTRIDE + c2] = pack_f16x2(v.x, v.y);
        }
    }
    // stage W1 cols [hbase, hbase+64) of the selected half, n-major
    {
        #pragma unroll
        for (int it = 0; it < 64; it++) {
            int e = tid + it * 256;       // 0..16383
            int k = e >> 6, n = e & 63;
            Ws_h[n * (2 * PSTRIDE) + k] =
                __float2half(W1[(size_t)(which * 256 + k) * HH + hbase + n]);
        }
    }
    __syncthreads();

    const int w = tid >> 5, lane = tid & 31;
    const int g = lane >> 2, t = lane & 3;
    const int wm = w & 1, wn = w >> 1;    // warp tile: 16M x 16N

    float c[2][4] = {{0.f,0.f,0.f,0.f},{0.f,0.f,0.f,0.f}};
    const uint32_t* A0 = As + (wm * 16 + g) * PSTRIDE;
    const uint32_t* A8 = A0 + 8 * PSTRIDE;
    const uint32_t* B0 = Ws + (wn * 16 + g) * PSTRIDE;
    const uint32_t* B8 = B0 + 8 * PSTRIDE;

    #pragma unroll
    for (int s = 0; s < 16; s++) {
        uint32_t a0 = A0[8 * s + t],     a1 = A8[8 * s + t];
        uint32_t a2 = A0[8 * s + t + 4], a3 = A8[8 * s + t + 4];
        mma16816(c[0], a0, a1, a2, a3, B0[8 * s + t], B0[8 * s + t + 4]);
        mma16816(c[1], a0, a1, a2, a3, B8[8 * s + t], B8[8 * s + t + 4]);
    }

    uint32_t* dst = which ? g_pj_h : g_pi_h;
    #pragma unroll
    for (int nt = 0; nt < 2; nt++) {
        float2 bias = make_float2(0.f, 0.f);
        if (which)
            bias = *(const float2*)(b1 + hbase + wn * 16 + nt * 8 + 2 * t);
        int cp = (ct & 1) * 32 + wn * 8 + nt * 4 + t;     // global colpair
        int r0 = row0 + wm * 16 + g;
        dst[(size_t)r0 * 64 + cp]       = pack_f16x2(c[nt][0] + bias.x, c[nt][1] + bias.y);
        dst[(size_t)(r0 + 8) * 64 + cp] = pack_f16x2(c[nt][2] + bias.x, c[nt][3] + bias.y);
    }
}

// -------------------------------------------------------------------------
// Phase B (HMMA): CTA = (jhalf, itile, b) = 256 CTAs, 8 warps; warp owns ONE
// 16-j tile. A = relu(pi+pj) built as f16x2 in fragment layout; m16n8k16,
// N=8=R exactly. 2 CTAs/SM for latency hiding; tanh-based sigmoid epilogue.
// -------------------------------------------------------------------------
#define PJ_STRIDE 68

__global__ __launch_bounds__(256, 2) void pair_mma_kernel(
    const float* __restrict__ W2,
    const float* __restrict__ b2,
    float* __restrict__ out)
{
    __shared__ uint32_t pj_s[128 * PJ_STRIDE];
    __shared__ uint32_t pi_s[16 * PJ_STRIDE];

    const int tid = threadIdx.x;
    const int w = tid >> 5, lane = tid & 31;
    const int g = lane >> 2, t = lane & 3;
    const int jhalf = blockIdx.x, itile = blockIdx.y, b = blockIdx.z;

    // stage pj (128 j rows of this half) + pi (16 i rows), u64 coalesced
    {
        const u64* src = (const u64*)(g_pj_h + (((size_t)b * NN + jhalf * 128) << 6));
        #pragma unroll
        for (int it = 0; it < 16; it++) {
            int e = tid + it * 256;        // 0..4095
            int row = e >> 5, c2 = e & 31;
            *(u64*)(pj_s + row * PJ_STRIDE + 2 * c2) = src[e];
        }
        const u64* si = (const u64*)(g_pi_h + (((size_t)b * NN + itile * 16) << 6));
        #pragma unroll
        for (int it = 0; it < 2; it++) {
            int e = tid + it * 256;        // 0..511
            int row = e >> 5, c2 = e & 31;
            *(u64*)(pi_s + row * PJ_STRIDE + 2 * c2) = si[e];
        }
    }

    // W2 fragments: b0 = {W2[k0][g], W2[k0+1][g]}, k0 = 16s+2t
    uint32_t w2f[8][2];
    #pragma unroll
    for (int s = 0; s < 8; s++) {
        int k0 = 16 * s + 2 * t;
        w2f[s][0] = pack_f16x2(W2[k0 * RR + g],       W2[(k0 + 1) * RR + g]);
        w2f[s][1] = pack_f16x2(W2[(k0 + 8) * RR + g], W2[(k0 + 9) * RR + g]);
    }
    const float2 b2v = *(const float2*)(b2 + 2 * t);
    const float hbx = 0.5f * b2v.x, hby = 0.5f * b2v.y;

    __syncthreads();

    // hoist pj fragments for this warp's jtile (rows w*16+g, +8)
    uint32_t pjf[8][4];
    {
        const uint32_t* r0 = pj_s + (w * 16 + g) * PJ_STRIDE;
        const uint32_t* r8 = r0 + 8 * PJ_STRIDE;
        #pragma unroll
        for (int s = 0; s < 8; s++) {
            pjf[s][0] = r0[t + 8 * s];
            pjf[s][1] = r8[t + 8 * s];
            pjf[s][2] = r0[t + 8 * s + 4];
            pjf[s][3] = r8[t + 8 * s + 4];
        }
    }

    const size_t obase = (((size_t)b * NN + itile * 16) * NN + jhalf * 128 + w * 16) * RR;

    #pragma unroll 2
    for (int i = 0; i < 16; i++) {
        uint32_t piv[16];
        {
            const uint32_t* pir = pi_s + i * PJ_STRIDE;
            #pragma unroll
            for (int s = 0; s < 8; s++) {
                piv[2 * s]     = pir[t + 8 * s];
                piv[2 * s + 1] = pir[t + 8 * s + 4];
            }
        }
        float d[4] = {0.f, 0.f, 0.f, 0.f};
        #pragma unroll
        for (int s = 0; s < 8; s++) {
            uint32_t lo = piv[2 * s], hi = piv[2 * s + 1];
            uint32_t a0 = hmax2(hadd2(pjf[s][0], lo), 0u);
            uint32_t a1 = hmax2(hadd2(pjf[s][1], lo), 0u);
            uint32_t a2 = hmax2(hadd2(pjf[s][2], hi), 0u);
            uint32_t a3 = hmax2(hadd2(pjf[s][3], hi), 0u);
            mma16816(d, a0, a1, a2, a3, w2f[s][0], w2f[s][1]);
        }
        float2 o0 = make_float2(sigm(d[0], hbx), sigm(d[1], hby));
        float2 o1 = make_float2(sigm(d[2], hbx), sigm(d[3], hby));
        float* op = out + obase + (size_t)i * NN * RR + 2 * t;
        *(float2*)(op + g * RR)       = o0;
        *(float2*)(op + (g + 8) * RR) = o1;
    }
}

extern "C" void kernel_launch(void* const* d_in, const int* in_sizes, int n_in,
                              void* d_out, int out_size)
{
    const float* slots = (const float*)d_in[0];
    const float* W1    = (const float*)d_in[1];
    const float* b1    = (const float*)d_in[2];
    const float* W2    = (const float*)d_in[3];
    const float* b2    = (const float*)d_in[4];
    float* out = (float*)d_out;

    cudaFuncSetAttribute(proj_kernel,
                         cudaFuncAttributeMaxDynamicSharedMemorySize, PROJ_SMEM);

    proj_kernel<<<dim3(4, 64), 256, PROJ_SMEM>>>(slots, W1, b1);
    pair_mma_kernel<<<dim3(2, 16, 8), 256>>>(W2, b2, out);
}

// round 7
// speedup vs baseline: 3.7434x; 1.1386x over previous
#include <cuda_runtime.h>
#include <cuda_fp16.h>
#include <cstdint>

#define NN 256
#define HH 128
#define RR 8

typedef unsigned long long u64;

// packed f16x2 proj outputs: [2048 rows][64 kpairs]; lo half = even k
__device__ uint32_t g_pi_h[2048 * 64];
__device__ uint32_t g_pj_h[2048 * 64];

// fragment-order position of kpair kp within a row (u32 index):
// slot (s = kp>>3, t' = kp&7): t'<4 -> word 8s+2t' (lo), t'>=4 -> word 8s+2(t'-4)+1 (hi)
#define FPOS(kp) ((((kp) >> 3) << 3) + (((kp) & 3) << 1) + (((kp) >> 2) & 1))

// ---------------- helpers ----------------
__device__ __forceinline__ uint32_t hadd2(uint32_t a, uint32_t b) {
    uint32_t d; asm("add.rn.f16x2 %0, %1, %2;" : "=r"(d) : "r"(a), "r"(b)); return d;
}
__device__ __forceinline__ uint32_t hmax2(uint32_t a, uint32_t b) {
    uint32_t d; asm("max.f16x2 %0, %1, %2;" : "=r"(d) : "r"(a), "r"(b)); return d;
}
__device__ __forceinline__ uint32_t pack_f16x2(float lo, float hi) {
    uint32_t d; asm("cvt.rn.f16x2.f32 %0, %1, %2;" : "=r"(d) : "f"(hi), "f"(lo)); return d;
}
__device__ __forceinline__ void mma16816(float* d, uint32_t a0, uint32_t a1,
                                         uint32_t a2, uint32_t a3,
                                         uint32_t b0, uint32_t b1) {
    asm("mma.sync.aligned.m16n8k16.row.col.f32.f16.f16.f32 "
        "{%0,%1,%2,%3}, {%4,%5,%6,%7}, {%8,%9}, {%0,%1,%2,%3};"
        : "+f"(d[0]), "+f"(d[1]), "+f"(d[2]), "+f"(d[3])
        : "r"(a0), "r"(a1), "r"(a2), "r"(a3), "r"(b0), "r"(b1));
}
// sigmoid(x) = 0.5 + 0.5*tanh(0.5*x); hb carries 0.5*b2 folded in
__device__ __forceinline__ float sigm(float x, float hb) {
    float t, a = fmaf(0.5f, x, hb);
    asm("tanh.approx.f32 %0, %1;" : "=f"(t) : "f"(a));
    return fmaf(0.5f, t, 0.5f);
}

// -------------------------------------------------------------------------
// Phase A (HMMA): proj = slots[2048,256] @ W1cat[256,256] (+b1 on pj half).
// CTA tile 32M x 64N, full K=256. grid (4 ct, 64 rt) x 256 thr.
// As: frag-order u64 rows (stride 68 u64 = 136 words, 136%32==8 -> LDS.64 CF)
// Ws: u32 [kp][n] rows stride 72 (72%32==8 -> frag LDS 8t+g CF; staging CF)
// Split accumulator chains (even/odd s).
// -------------------------------------------------------------------------
#define A_STR64 68               // u64 stride (136 u32 words)
#define W_STR 72                 // u32 stride
#define PROJ_SMEM (32 * A_STR64 * 8 + 128 * W_STR * 4)

__global__ __launch_bounds__(256) void proj_kernel(
    const float* __restrict__ slots,
    const float* __restrict__ W1,
    const float* __restrict__ b1)
{
    extern __shared__ __align__(16) u64 psm[];
    uint32_t* Asw = (uint32_t*)psm;              // 32 rows x 136 words
    uint32_t* Ws  = (uint32_t*)(psm + 32 * A_STR64);  // 128 kp x 72 words

    const int tid = threadIdx.x;
    const int ct = blockIdx.x, rt = blockIdx.y;
    const int row0 = rt * 32;
    const int which = ct >> 1;            // 0 -> pi, 1 -> pj
    const int hbase = (ct & 1) * 64;

    // stage slots rows [row0, row0+32): f16x2 in fragment order
    {
        const float2* sp = (const float2*)(slots + (size_t)row0 * 256);
        #pragma unroll
        for (int it = 0; it < 16; it++) {
            int e = tid + it * 256;       // 0..4095
            int r = e >> 7, c2 = e & 127;
            float2 v = sp[r * 128 + c2];
            Asw[r * 136 + FPOS(c2)] = pack_f16x2(v.x, v.y);
        }
    }
    // stage W1 half, cols [hbase,hbase+64): u32 {W1[2kp][n], W1[2kp+1][n]} at [kp][n]
    {
        #pragma unroll
        for (int it = 0; it < 16; it++) {
            int e = tid + it * 256;       // 0..4095
            int kp = e >> 5, n2 = e & 31;
            const float* wb = W1 + (size_t)(which * 256 + 2 * kp) * HH + hbase + 2 * n2;
            float2 f0 = *(const float2*)wb;
            float2 f1 = *(const float2*)(wb + HH);
            u64 two = ((u64)pack_f16x2(f0.y, f1.y) << 32) | pack_f16x2(f0.x, f1.x);
            *(u64*)(Ws + kp * W_STR + 2 * n2) = two;
        }
    }
    __syncthreads();

    const int w = tid >> 5, lane = tid & 31;
    const int g = lane >> 2, t = lane & 3;
    const int wm = w & 1, wn = w >> 1;    // warp tile: 16M x 16N

    float ce[2][4] = {{0.f,0.f,0.f,0.f},{0.f,0.f,0.f,0.f}};
    float co[2][4] = {{0.f,0.f,0.f,0.f},{0.f,0.f,0.f,0.f}};
    const uint32_t* Ar0 = Asw + (wm * 16 + g) * 136;
    const uint32_t* Ar8 = Ar0 + 8 * 136;
    const int n0 = wn * 16 + g;

    #pragma unroll
    for (int s = 0; s < 16; s++) {
        u64 av0 = *(const u64*)(Ar0 + 8 * s + 2 * t);   // {a0, a2}
        u64 av8 = *(const u64*)(Ar8 + 8 * s + 2 * t);   // {a1, a3}
        uint32_t a0 = (uint32_t)av0, a2 = (uint32_t)(av0 >> 32);
        uint32_t a1 = (uint32_t)av8, a3 = (uint32_t)(av8 >> 32);
        const uint32_t* B0 = Ws + (8 * s + t) * W_STR;
        const uint32_t* B4 = B0 + 4 * W_STR;
        float* c0 = (s & 1) ? co[0] : ce[0];
        float* c1 = (s & 1) ? co[1] : ce[1];
        mma16816(c0, a0, a1, a2, a3, B0[n0],     B4[n0]);
        mma16816(c1, a0, a1, a2, a3, B0[n0 + 8], B4[n0 + 8]);
    }

    uint32_t* dst = which ? g_pj_h : g_pi_h;
    #pragma unroll
    for (int nt = 0; nt < 2; nt++) {
        float2 bias = make_float2(0.f, 0.f);
        if (which)
            bias = *(const float2*)(b1 + hbase + wn * 16 + nt * 8 + 2 * t);
        float c0 = ce[nt][0] + co[nt][0] + bias.x;
        float c1 = ce[nt][1] + co[nt][1] + bias.y;
        float c2 = ce[nt][2] + co[nt][2] + bias.x;
        float c3 = ce[nt][3] + co[nt][3] + bias.y;
        int cp = (ct & 1) * 32 + wn * 8 + nt * 4 + t;     // global colpair
        int r0 = row0 + wm * 16 + g;
        dst[(size_t)r0 * 64 + cp]       = pack_f16x2(c0, c1);
        dst[(size_t)(r0 + 8) * 64 + cp] = pack_f16x2(c2, c3);
    }
}

// -------------------------------------------------------------------------
// Phase B (HMMA): CTA = (jhalf, itile, b) = 256 CTAs, 8 warps, warp owns one
// 16-j tile. pi/pj staged frag-ordered u64 (stride 36 u64 = 72 words,
// 72%32==8 -> LDS.64 conflict-free; piv loads broadcast). Split d chains.
// -------------------------------------------------------------------------
#define P_STR64 36               // u64 stride (72 words) for 32-u64 rows

__global__ __launch_bounds__(256, 2) void pair_mma_kernel(
    const float* __restrict__ W2,
    const float* __restrict__ b2,
    float* __restrict__ out)
{
    __shared__ __align__(16) u64 pj_s[128 * P_STR64];
    __shared__ __align__(16) u64 pi_s[16 * P_STR64];
    uint32_t* pjw = (uint32_t*)pj_s;
    uint32_t* piw = (uint32_t*)pi_s;

    const int tid = threadIdx.x;
    const int w = tid >> 5, lane = tid & 31;
    const int g = lane >> 2, t = lane & 3;
    const int jhalf = blockIdx.x, itile = blockIdx.y, b = blockIdx.z;

    // stage pj/pi in fragment order (2x STS.32 per u64 source chunk)
    {
        const u64* src = (const u64*)(g_pj_h + (((size_t)b * NN + jhalf * 128) << 6));
        #pragma unroll
        for (int it = 0; it < 16; it++) {
            int e = tid + it * 256;        // 0..4095
            int row = e >> 5, m = e & 31;
            u64 v = src[e];
            pjw[row * 72 + FPOS(2 * m)]     = (uint32_t)v;
            pjw[row * 72 + FPOS(2 * m + 1)] = (uint32_t)(v >> 32);
        }
        const u64* si = (const u64*)(g_pi_h + (((size_t)b * NN + itile * 16) << 6));
        #pragma unroll
        for (int it = 0; it < 2; it++) {
            int e = tid + it * 256;        // 0..511
            int row = e >> 5, m = e & 31;
            u64 v = si[e];
            piw[row * 72 + FPOS(2 * m)]     = (uint32_t)v;
            piw[row * 72 + FPOS(2 * m + 1)] = (uint32_t)(v >> 32);
        }
    }

    // W2 fragments: b0 = {W2[k0][g], W2[k0+1][g]}, k0 = 16s+2t
    uint32_t w2f[8][2];
    #pragma unroll
    for (int s = 0; s < 8; s++) {
        int k0 = 16 * s + 2 * t;
        w2f[s][0] = pack_f16x2(W2[k0 * RR + g],       W2[(k0 + 1) * RR + g]);
        w2f[s][1] = pack_f16x2(W2[(k0 + 8) * RR + g], W2[(k0 + 9) * RR + g]);
    }
    const float2 b2v = *(const float2*)(b2 + 2 * t);
    const float hbx = 0.5f * b2v.x, hby = 0.5f * b2v.y;

    __syncthreads();

    // hoist pj fragments for this warp's jtile: pjf[s][0]={row g lo,hi}, [1]={row g+8}
    u64 pjf[8][2];
    {
        const uint32_t* r0 = pjw + (w * 16 + g) * 72;
        const uint32_t* r8 = r0 + 8 * 72;
        #pragma unroll
        for (int s = 0; s < 8; s++) {
            pjf[s][0] = *(const u64*)(r0 + 8 * s + 2 * t);
            pjf[s][1] = *(const u64*)(r8 + 8 * s + 2 * t);
        }
    }

    const size_t obase = (((size_t)b * NN + itile * 16) * NN + jhalf * 128 + w * 16) * RR;

    #pragma unroll 2
    for (int i = 0; i < 16; i++) {
        const uint32_t* pir = piw + i * 72;
        float da[4] = {0.f, 0.f, 0.f, 0.f};
        float db[4] = {0.f, 0.f, 0.f, 0.f};
        #pragma unroll
        for (int s = 0; s < 8; s++) {
            u64 pv = *(const u64*)(pir + 8 * s + 2 * t);   // broadcast LDS.64
            uint32_t lo = (uint32_t)pv, hi = (uint32_t)(pv >> 32);
            u64 pj0 = pjf[s][0], pj1 = pjf[s][1];
            uint32_t a0 = hmax2(hadd2((uint32_t)pj0, lo), 0u);
            uint32_t a1 = hmax2(hadd2((uint32_t)pj1, lo), 0u);
            uint32_t a2 = hmax2(hadd2((uint32_t)(pj0 >> 32), hi), 0u);
            uint32_t a3 = hmax2(hadd2((uint32_t)(pj1 >> 32), hi), 0u);
            mma16816((s & 1) ? db : da, a0, a1, a2, a3, w2f[s][0], w2f[s][1]);
        }
        float2 o0 = make_float2(sigm(da[0] + db[0], hbx), sigm(da[1] + db[1], hby));
        float2 o1 = make_float2(sigm(da[2] + db[2], hbx), sigm(da[3] + db[3], hby));
        float* op = out + obase + (size_t)i * NN * RR + 2 * t;
        *(float2*)(op + g * RR)       = o0;
        *(float2*)(op + (g + 8) * RR) = o1;
    }
}

extern "C" void kernel_launch(void* const* d_in, const int* in_sizes, int n_in,
                              void* d_out, int out_size)
{
    const float* slots = (const float*)d_in[0];
    const float* W1    = (const float*)d_in[1];
    const float* b1    = (const float*)d_in[2];
    const float* W2    = (const float*)d_in[3];
    const float* b2    = (const float*)d_in[4];
    float* out = (float*)d_out;

    cudaFuncSetAttribute(proj_kernel,
                         cudaFuncAttributeMaxDynamicSharedMemorySize, PROJ_SMEM);

    proj_kernel<<<dim3(4, 64), 256, PROJ_SMEM>>>(slots, W1, b1);
    pair_mma_kernel<<<dim3(2, 16, 8), 256>>>(W2, b2, out);
}